// round 9
// baseline (speedup 1.0000x reference)
#include <cuda_runtime.h>
#include <math.h>

#define N_NODES 100000
#define N_EDGES 3200000
#define F_IN    256
#define F_HID   16
#define F_OUT   40

typedef unsigned long long u64;

// ---- static scratch (no allocations allowed; zero-initialized at load) ----
// Invariant maintained across calls: g_cnt == 0 and g_base == 0 on entry
// (restored by k_scan / k_fill after last use each call).
__device__ float g_hs  [N_NODES * F_HID];  // pass-1 gather source (dinv * xW1)
__device__ float g_hs2 [N_NODES * F_HID];  // pass-2 gather source
__device__ float g_dinv[N_NODES];
__device__ int   g_cnt [N_NODES];          // in-degree scratch (zero on entry)
__device__ int   g_fill[N_NODES];          // cursor; scan sets = rowp, fill -> row end
__device__ int   g_rowp[N_NODES];          // absolute row start in g_csr
__device__ int   g_csr [N_EDGES];          // src ids grouped by dst
__device__ int   g_base;                   // global CSR offset counter (zero on entry)

// ---- packed f32x2 helpers (Blackwell sm_100a) ----
__device__ __forceinline__ u64 pack2(float lo, float hi) {
    u64 r; asm("mov.b64 %0, {%1, %2};" : "=l"(r) : "f"(lo), "f"(hi)); return r;
}
__device__ __forceinline__ void fma2(u64& d, u64 a, u64 b) {
    asm("fma.rn.f32x2 %0, %1, %2, %0;" : "+l"(d) : "l"(a), "l"(b));
}
__device__ __forceinline__ void mul2(u64& d, u64 a, u64 b) {
    asm("mul.rn.f32x2 %0, %1, %2;" : "=l"(d) : "l"(a), "l"(b));
}

// ---------------------------------------------------------------------------
// Inline edge-index dtype detection (per block, no global dependency).
// ---------------------------------------------------------------------------
__device__ __forceinline__ int detect_is64_block(const void* ei) {
    __shared__ int s_is64;
    if (threadIdx.x == 0) {
        const long long* p = (const long long*)ei;
        int ok = 1;
#pragma unroll
        for (int j = 0; j < 8; j++) {
            long long v = p[j];
            if (v < 0 || v >= (long long)N_NODES) ok = 0;
        }
        s_is64 = ok;
    }
    __syncthreads();
    return s_is64;
}

__device__ __forceinline__ int edge_at(const void* ei, int is64, long long pos) {
    if (is64) return (int)((const long long*)ei)[pos];
    return ((const int*)ei)[pos];
}

// ---------------------------------------------------------------------------
// In-degree count
// ---------------------------------------------------------------------------
__global__ void k_count(const void* __restrict__ ei) {
    int is64 = detect_is64_block(ei);
    int stride = gridDim.x * 256;
    for (int e = blockIdx.x * 256 + threadIdx.x; e < N_EDGES; e += stride) {
        int d = edge_at(ei, is64, (long long)N_EDGES + e);
        atomicAdd(&g_cnt[d], 1);
    }
}

// ---------------------------------------------------------------------------
// Exclusive scan; seeds fill cursor = rowp; dinv; re-zeroes g_cnt.
// ---------------------------------------------------------------------------
__global__ void k_scan() {
    __shared__ int wtot[32];
    __shared__ int sbase;
    int tid  = threadIdx.x;
    int lane = tid & 31, wid = tid >> 5;
    int gid  = blockIdx.x * 1024 + tid;

    int v = (gid < N_NODES) ? g_cnt[gid] : 0;
    int x = v;
#pragma unroll
    for (int off = 1; off < 32; off <<= 1) {
        int t = __shfl_up_sync(0xffffffffu, x, off);
        if (lane >= off) x += t;
    }
    if (lane == 31) wtot[wid] = x;
    __syncthreads();
    if (wid == 0) {
        int w = wtot[lane];
        int y = w;
#pragma unroll
        for (int off = 1; off < 32; off <<= 1) {
            int t = __shfl_up_sync(0xffffffffu, y, off);
            if (lane >= off) y += t;
        }
        wtot[lane] = y - w;
        if (lane == 31) sbase = atomicAdd(&g_base, y);
    }
    __syncthreads();
    if (gid < N_NODES) {
        int rp = sbase + wtot[wid] + (x - v);
        g_rowp[gid] = rp;
        g_fill[gid] = rp;
        g_dinv[gid] = rsqrtf((float)(v + 1));
        g_cnt[gid]  = 0;
    }
}

// ---------------------------------------------------------------------------
// CSR fill: slot = atomicAdd(&fill[d],1) is ABSOLUTE. fill[n] -> row end.
// ---------------------------------------------------------------------------
__global__ void k_fill(const void* __restrict__ ei) {
    int is64 = detect_is64_block(ei);
    if (blockIdx.x == 0 && threadIdx.x == 0) g_base = 0;
    int stride = gridDim.x * 256;
    for (int e = blockIdx.x * 256 + threadIdx.x; e < N_EDGES; e += stride) {
        int s = edge_at(ei, is64, e);
        int d = edge_at(ei, is64, (long long)N_EDGES + e);
        int slot = atomicAdd(&g_fill[d], 1);
        g_csr[slot] = s;
    }
}

// ---------------------------------------------------------------------------
// Layer-1 GEMM v4: hs[i,:] = dinv[i] * (x[i,:] @ W1).
// 256 threads/block, 1 node/thread (grid 391 -> ~21 warps/SM).
// Coalesced staging loads (warp = 512B contiguous, nL=4) into a TRANSPOSED
// double-buffered smem tile xs[2][16][256]: both STS (lanes = consecutive n,
// 256-float stride between c rows) and LDS (xs[c][tid]) are conflict-free
// with NO padding, so both buffers + W1s fit exactly in 48KB static smem.
// One __syncthreads per chunk; next chunk's LDGs issue before the sync and
// are consumed a full compute phase later. Math in packed f32x2.
// ---------------------------------------------------------------------------
__global__ void __launch_bounds__(256)
k_gemm1(const float* __restrict__ x, const float* __restrict__ W1) {
    __shared__ float W1s[F_IN * F_HID];      // 16 KB
    __shared__ float xs[2][16][256];         // 32 KB (2 chunk buffers, transposed)

    int tid = threadIdx.x;
    {
        const float4* src = (const float4*)W1;
        float4* dst = (float4*)W1s;
#pragma unroll
        for (int r = 0; r < 4; r++) dst[tid + r * 256] = src[tid + r * 256];
    }

    int node0 = blockIdx.x * 256;
    int node  = node0 + tid;

    // staging map: i = tid + r*256 -> stages node (i>>2), float4 (i&3) of the chunk
    int sn = tid >> 2, sc = tid & 3;         // r folds in below

    // prefetch chunk 0 (4 float4 per thread, coalesced)
    float4 pr[4];
#pragma unroll
    for (int r = 0; r < 4; r++) {
        int n = sn + r * 64;
        pr[r] = (node0 + n < N_NODES)
              ? *(const float4*)(x + (size_t)(node0 + n) * F_IN + sc * 4)
              : make_float4(0.f, 0.f, 0.f, 0.f);
    }
    __syncthreads();                          // W1s ready

    u64 acc[8];
#pragma unroll
    for (int j = 0; j < 8; j++) acc[j] = 0ull;

    int b = 0;
    const float* wp = W1s;
    for (int kc = 0; kc < F_IN; kc += 16) {
        // stage current chunk (transposed: xs[b][col][node])
#pragma unroll
        for (int r = 0; r < 4; r++) {
            int n = sn + r * 64;
            xs[b][sc * 4 + 0][n] = pr[r].x;
            xs[b][sc * 4 + 1][n] = pr[r].y;
            xs[b][sc * 4 + 2][n] = pr[r].z;
            xs[b][sc * 4 + 3][n] = pr[r].w;
        }
        // prefetch next chunk before the barrier (consumed next iteration)
        if (kc + 16 < F_IN) {
#pragma unroll
            for (int r = 0; r < 4; r++) {
                int n = sn + r * 64;
                pr[r] = (node0 + n < N_NODES)
                      ? *(const float4*)(x + (size_t)(node0 + n) * F_IN + kc + 16 + sc * 4)
                      : make_float4(0.f, 0.f, 0.f, 0.f);
            }
        }
        __syncthreads();

#pragma unroll
        for (int c = 0; c < 16; c++) {
            float xv = xs[b][c][tid];
            const ulonglong2* wq = (const ulonglong2*)(wp + c * F_HID);
            ulonglong2 w0 = wq[0], w1 = wq[1], w2 = wq[2], w3 = wq[3];
            u64 xp = pack2(xv, xv);
            fma2(acc[0], xp, w0.x);
            fma2(acc[1], xp, w0.y);
            fma2(acc[2], xp, w1.x);
            fma2(acc[3], xp, w1.y);
            fma2(acc[4], xp, w2.x);
            fma2(acc[5], xp, w2.y);
            fma2(acc[6], xp, w3.x);
            fma2(acc[7], xp, w3.y);
        }
        wp += 16 * F_HID;
        b ^= 1;
    }

    if (node < N_NODES) {
        u64 dv = pack2(g_dinv[node], g_dinv[node]);
        ulonglong2* row = (ulonglong2*)(g_hs + (size_t)node * F_HID);
#pragma unroll
        for (int p = 0; p < 4; p++) {
            ulonglong2 o;
            mul2(o.x, acc[2 * p], dv);
            mul2(o.y, acc[2 * p + 1], dv);
            row[p] = o;
        }
    }
}

// ---------------------------------------------------------------------------
// Vectorized warp gather (unchanged).
// ---------------------------------------------------------------------------
__device__ __forceinline__ float4 warp_gather(const float4* __restrict__ src4,
                                              const int* __restrict__ csr,
                                              int rs, int re, int eo, int q) {
    float4 a0 = make_float4(0.f, 0.f, 0.f, 0.f);
    float4 a1 = make_float4(0.f, 0.f, 0.f, 0.f);
    for (int base = rs; base < re; base += 16) {
        int i0 = base + eo, i1 = base + 8 + eo;
        if (i0 < re) {
            int s = __ldg(&csr[i0]);
            float4 v = src4[(size_t)s * 4 + q];
            a0.x += v.x; a0.y += v.y; a0.z += v.z; a0.w += v.w;
        }
        if (i1 < re) {
            int s = __ldg(&csr[i1]);
            float4 v = src4[(size_t)s * 4 + q];
            a1.x += v.x; a1.y += v.y; a1.z += v.z; a1.w += v.w;
        }
    }
    a0.x += a1.x; a0.y += a1.y; a0.z += a1.z; a0.w += a1.w;
#pragma unroll
    for (int off = 4; off < 32; off <<= 1) {
        a0.x += __shfl_xor_sync(0xffffffffu, a0.x, off);
        a0.y += __shfl_xor_sync(0xffffffffu, a0.y, off);
        a0.z += __shfl_xor_sync(0xffffffffu, a0.z, off);
        a0.w += __shfl_xor_sync(0xffffffffu, a0.w, off);
    }
    return a0;
}

// ---------------------------------------------------------------------------
// Gather pass 1 + fused mid: hs2 = dinv * relu(dinv*(sum + self) + b1)
// ---------------------------------------------------------------------------
__global__ void k_gather1(const float* __restrict__ b1) {
    int tid = threadIdx.x, lane = tid & 31;
    int n = blockIdx.x * 8 + (tid >> 5);
    int eo = lane >> 2, q = lane & 3;
    int rs = g_rowp[n], re = g_fill[n];

    float4 a = warp_gather((const float4*)g_hs, g_csr, rs, re, eo, q);

    float4 sv = ((const float4*)g_hs)[(size_t)n * 4 + q];
    float di = g_dinv[n];
    float4 b = *(const float4*)(b1 + q * 4);
    float4 r;
    r.x = fmaxf(fmaf(di, a.x + sv.x, b.x), 0.f) * di;
    r.y = fmaxf(fmaf(di, a.y + sv.y, b.y), 0.f) * di;
    r.z = fmaxf(fmaf(di, a.z + sv.z, b.z), 0.f) * di;
    r.w = fmaxf(fmaf(di, a.w + sv.w, b.w), 0.f) * di;
    if (lane < 4) ((float4*)g_hs2)[(size_t)n * 4 + lane] = r;
}

// ---------------------------------------------------------------------------
// Gather pass 2 fused with GEMM2 + log_softmax
// ---------------------------------------------------------------------------
__global__ void k_gather2_final(const float* __restrict__ W2,
                                const float* __restrict__ b2,
                                float* __restrict__ out) {
    __shared__ float W2s[F_HID * F_OUT];
    __shared__ float b2s[F_OUT];
    int tid = threadIdx.x;
    for (int i = tid; i < F_HID * F_OUT; i += 256) W2s[i] = W2[i];
    if (tid < F_OUT) b2s[tid] = b2[tid];
    __syncthreads();

    int lane = tid & 31;
    int n = blockIdx.x * 8 + (tid >> 5);
    int eo = lane >> 2, q = lane & 3;
    int rs = g_rowp[n], re = g_fill[n];

    float4 a = warp_gather((const float4*)g_hs2, g_csr, rs, re, eo, q);

    float4 sv = ((const float4*)g_hs2)[(size_t)n * 4 + q];
    float di = g_dinv[n];
    float4 av;
    av.x = di * (a.x + sv.x); av.y = di * (a.y + sv.y);
    av.z = di * (a.z + sv.z); av.w = di * (a.w + sv.w);

    int jA = lane, jB = lane + 32;
    float l0 = b2s[jA];
    float l1 = (jB < F_OUT) ? b2s[jB] : -3.0e38f;
#pragma unroll
    for (int kq = 0; kq < 4; kq++) {
        float c0 = __shfl_sync(0xffffffffu, av.x, kq);
        float c1 = __shfl_sync(0xffffffffu, av.y, kq);
        float c2 = __shfl_sync(0xffffffffu, av.z, kq);
        float c3 = __shfl_sync(0xffffffffu, av.w, kq);
        const float* w = W2s + (kq * 4) * F_OUT;
        l0 = fmaf(c0, w[jA],             l0);
        l0 = fmaf(c1, w[F_OUT + jA],     l0);
        l0 = fmaf(c2, w[2 * F_OUT + jA], l0);
        l0 = fmaf(c3, w[3 * F_OUT + jA], l0);
        if (jB < F_OUT) {
            l1 = fmaf(c0, w[jB],             l1);
            l1 = fmaf(c1, w[F_OUT + jB],     l1);
            l1 = fmaf(c2, w[2 * F_OUT + jB], l1);
            l1 = fmaf(c3, w[3 * F_OUT + jB], l1);
        }
    }

    float m = fmaxf(l0, l1);
#pragma unroll
    for (int off = 16; off > 0; off >>= 1)
        m = fmaxf(m, __shfl_xor_sync(0xffffffffu, m, off));
    float s = expf(l0 - m) + ((jB < F_OUT) ? expf(l1 - m) : 0.f);
#pragma unroll
    for (int off = 16; off > 0; off >>= 1)
        s += __shfl_xor_sync(0xffffffffu, s, off);
    float lse = m + logf(s);

    float* op = out + (size_t)n * F_OUT;
    op[jA] = l0 - lse;
    if (jB < F_OUT) op[jB] = l1 - lse;
}

// ---------------------------------------------------------------------------
extern "C" void kernel_launch(void* const* d_in, const int* in_sizes, int n_in,
                              void* d_out, int out_size) {
    const float* x  = (const float*)d_in[0];
    const void*  ei = d_in[1];
    const float* W1 = (const float*)d_in[2];
    const float* b1 = (const float*)d_in[3];
    const float* W2 = (const float*)d_in[4];
    const float* b2 = (const float*)d_in[5];
    float* out = (float*)d_out;

    k_count<<<6250, 256>>>(ei);
    k_scan<<<(N_NODES + 1023) / 1024, 1024>>>();
    k_fill<<<6250, 256>>>(ei);
    k_gemm1<<<(N_NODES + 255) / 256, 256>>>(x, W1);     // 256 nodes/block, 1/thread
    k_gather1<<<N_NODES / 8, 256>>>(b1);
    k_gather2_final<<<N_NODES / 8, 256>>>(W2, b2, out);
}

// round 12
// speedup vs baseline: 1.0519x; 1.0519x over previous
#include <cuda_runtime.h>
#include <math.h>

#define N_NODES 100000
#define N_EDGES 3200000
#define F_IN    256
#define F_HID   16
#define F_OUT   40
#define NB_GEMM 391              // gemm blocks in fused kernel (256 nodes each)
#define NB_CNT  6250             // count blocks in fused kernel (128 thr each)

typedef unsigned long long u64;

// ---- static scratch (no allocations allowed; zero-initialized at load) ----
// Invariant: g_cnt == 0 and g_base == 0 on entry (restored each call).
__device__ float g_hs  [N_NODES * F_HID];  // raw xW1, then dinv-scaled by k_scan
__device__ float g_hs2 [N_NODES * F_HID];  // pass-2 gather source
__device__ float g_dinv[N_NODES];
__device__ int   g_cnt [N_NODES];
__device__ int   g_fill[N_NODES];          // cursor; scan sets = rowp, fill -> row end
__device__ int   g_rowp[N_NODES];
__device__ int   g_csr [N_EDGES];
__device__ int   g_base;

// ---- packed f32x2 helpers (Blackwell sm_100a) ----
__device__ __forceinline__ u64 pack2(float lo, float hi) {
    u64 r; asm("mov.b64 %0, {%1, %2};" : "=l"(r) : "f"(lo), "f"(hi)); return r;
}
__device__ __forceinline__ void fma2(u64& d, u64 a, u64 b) {
    asm("fma.rn.f32x2 %0, %1, %2, %0;" : "+l"(d) : "l"(a), "l"(b));
}
__device__ __forceinline__ void mul2(u64& d, u64 a, u64 b) {
    asm("mul.rn.f32x2 %0, %1, %2;" : "=l"(d) : "l"(a), "l"(b));
}

// ---------------------------------------------------------------------------
// Edge-index dtype detection (per block; uniform branch).
// int64 data: first 8 values in [0, N_NODES). int32 data reinterpreted as
// int64 passes only if 8 independent high words are all zero (P ~ 1e-40).
// ---------------------------------------------------------------------------
__device__ __forceinline__ int detect_is64_block(const void* ei) {
    __shared__ int s_is64;
    if (threadIdx.x == 0) {
        const long long* p = (const long long*)ei;
        int ok = 1;
#pragma unroll
        for (int j = 0; j < 8; j++) {
            long long v = p[j];
            if (v < 0 || v >= (long long)N_NODES) ok = 0;
        }
        s_is64 = ok;
    }
    __syncthreads();
    return s_is64;
}

__device__ __forceinline__ int edge_at(const void* ei, int is64, long long pos) {
    if (is64) return (int)((const long long*)ei)[pos];
    return ((const int*)ei)[pos];
}

// ---------------------------------------------------------------------------
// FUSED kernel A: blocks [0, NB_GEMM) compute raw h = x @ W1 (no dinv yet);
// blocks [NB_GEMM, NB_GEMM+NB_CNT) count in-degrees. Disjoint state, distinct
// pipes (fma/L1 vs LSU/atomic) -> co-resident overlap.
// gemm part: 128 thr, 2 nodes/thread, barrier-free streaming (R8 layout).
// ---------------------------------------------------------------------------
__global__ void __launch_bounds__(128)
k_a(const float* __restrict__ x, const float* __restrict__ W1,
    const void* __restrict__ ei) {
    __shared__ float W1s[F_IN * F_HID];      // 16 KB (reserved by all blocks)

    if (blockIdx.x >= NB_GEMM) {
        // ---- count part ----
        int is64 = detect_is64_block(ei);
        int b = blockIdx.x - NB_GEMM;
        int stride = NB_CNT * 128;
        for (int e = b * 128 + threadIdx.x; e < N_EDGES; e += stride) {
            int d = edge_at(ei, is64, (long long)N_EDGES + e);
            atomicAdd(&g_cnt[d], 1);
        }
        return;
    }

    // ---- gemm part ----
    int tid = threadIdx.x;
    {
        const float4* src = (const float4*)W1;
        float4* dst = (float4*)W1s;
#pragma unroll
        for (int r = 0; r < 8; r++) dst[tid + r * 128] = src[tid + r * 128];
    }
    __syncthreads();

    int nodeA = blockIdx.x * 256 + tid;
    int nodeB = nodeA + 128;
    int vB = nodeB < N_NODES;                 // nodeA always < N_NODES
    const float4* xA = (const float4*)(x + (size_t)nodeA * F_IN);
    const float4* xB = (const float4*)(x + (size_t)(vB ? nodeB : 0) * F_IN);

    u64 accA[8], accB[8];
#pragma unroll
    for (int j = 0; j < 8; j++) { accA[j] = 0ull; accB[j] = 0ull; }

    const float* wp = W1s;
    for (int kc = 0; kc < F_IN; kc += 16) {
        float ar[16], br[16];
#pragma unroll
        for (int r = 0; r < 4; r++) {
            ((float4*)ar)[r] = xA[r];
            ((float4*)br)[r] = xB[r];
        }
        xA += 4; xB += 4;
#pragma unroll
        for (int c = 0; c < 16; c++) {
            const ulonglong2* wq = (const ulonglong2*)(wp + c * F_HID);
            ulonglong2 w0 = wq[0], w1 = wq[1], w2 = wq[2], w3 = wq[3];
            u64 xa = pack2(ar[c], ar[c]);
            u64 xb = pack2(br[c], br[c]);
            fma2(accA[0], xa, w0.x); fma2(accB[0], xb, w0.x);
            fma2(accA[1], xa, w0.y); fma2(accB[1], xb, w0.y);
            fma2(accA[2], xa, w1.x); fma2(accB[2], xb, w1.x);
            fma2(accA[3], xa, w1.y); fma2(accB[3], xb, w1.y);
            fma2(accA[4], xa, w2.x); fma2(accB[4], xb, w2.x);
            fma2(accA[5], xa, w2.y); fma2(accB[5], xb, w2.y);
            fma2(accA[6], xa, w3.x); fma2(accB[6], xb, w3.x);
            fma2(accA[7], xa, w3.y); fma2(accB[7], xb, w3.y);
        }
        wp += 16 * F_HID;
    }

    {
        ulonglong2* row = (ulonglong2*)(g_hs + (size_t)nodeA * F_HID);
#pragma unroll
        for (int p = 0; p < 4; p++) {
            ulonglong2 o; o.x = accA[2 * p]; o.y = accA[2 * p + 1];
            row[p] = o;
        }
    }
    if (vB) {
        ulonglong2* row = (ulonglong2*)(g_hs + (size_t)nodeB * F_HID);
#pragma unroll
        for (int p = 0; p < 4; p++) {
            ulonglong2 o; o.x = accB[2 * p]; o.y = accB[2 * p + 1];
            row[p] = o;
        }
    }
}

// ---------------------------------------------------------------------------
// Scan: exclusive prefix over cnt (block base via atomicAdd), seeds fill
// cursor = rowp, computes dinv, re-zeroes g_cnt, AND applies the deferred
// dinv scaling to g_hs (gemm wrote raw xW1).
// ---------------------------------------------------------------------------
__global__ void k_scan() {
    __shared__ int wtot[32];
    __shared__ int sbase;
    int tid  = threadIdx.x;
    int lane = tid & 31, wid = tid >> 5;
    int gid  = blockIdx.x * 1024 + tid;

    int v = (gid < N_NODES) ? g_cnt[gid] : 0;
    int x = v;
#pragma unroll
    for (int off = 1; off < 32; off <<= 1) {
        int t = __shfl_up_sync(0xffffffffu, x, off);
        if (lane >= off) x += t;
    }
    if (lane == 31) wtot[wid] = x;
    __syncthreads();
    if (wid == 0) {
        int w = wtot[lane];
        int y = w;
#pragma unroll
        for (int off = 1; off < 32; off <<= 1) {
            int t = __shfl_up_sync(0xffffffffu, y, off);
            if (lane >= off) y += t;
        }
        wtot[lane] = y - w;
        if (lane == 31) sbase = atomicAdd(&g_base, y);
    }
    __syncthreads();
    if (gid < N_NODES) {
        int rp = sbase + wtot[wid] + (x - v);
        g_rowp[gid] = rp;
        g_fill[gid] = rp;
        float d = rsqrtf((float)(v + 1));
        g_dinv[gid] = d;
        g_cnt[gid]  = 0;
        // deferred dinv scaling of h
        u64 dv = pack2(d, d);
        ulonglong2* row = (ulonglong2*)(g_hs + (size_t)gid * F_HID);
#pragma unroll
        for (int p = 0; p < 4; p++) {
            ulonglong2 o = row[p];
            mul2(o.x, o.x, dv);
            mul2(o.y, o.y, dv);
            row[p] = o;
        }
    }
}

// ---------------------------------------------------------------------------
// CSR fill: slot = atomicAdd(&fill[d],1) is ABSOLUTE. fill[n] -> row end.
// ---------------------------------------------------------------------------
__global__ void k_fill(const void* __restrict__ ei) {
    int is64 = detect_is64_block(ei);
    if (blockIdx.x == 0 && threadIdx.x == 0) g_base = 0;
    int stride = gridDim.x * 256;
    for (int e = blockIdx.x * 256 + threadIdx.x; e < N_EDGES; e += stride) {
        int s = edge_at(ei, is64, e);
        int d = edge_at(ei, is64, (long long)N_EDGES + e);
        int slot = atomicAdd(&g_fill[d], 1);
        g_csr[slot] = s;
    }
}

// ---------------------------------------------------------------------------
// Vectorized warp gather (unchanged).
// ---------------------------------------------------------------------------
__device__ __forceinline__ float4 warp_gather(const float4* __restrict__ src4,
                                              const int* __restrict__ csr,
                                              int rs, int re, int eo, int q) {
    float4 a0 = make_float4(0.f, 0.f, 0.f, 0.f);
    float4 a1 = make_float4(0.f, 0.f, 0.f, 0.f);
    for (int base = rs; base < re; base += 16) {
        int i0 = base + eo, i1 = base + 8 + eo;
        if (i0 < re) {
            int s = __ldg(&csr[i0]);
            float4 v = src4[(size_t)s * 4 + q];
            a0.x += v.x; a0.y += v.y; a0.z += v.z; a0.w += v.w;
        }
        if (i1 < re) {
            int s = __ldg(&csr[i1]);
            float4 v = src4[(size_t)s * 4 + q];
            a1.x += v.x; a1.y += v.y; a1.z += v.z; a1.w += v.w;
        }
    }
    a0.x += a1.x; a0.y += a1.y; a0.z += a1.z; a0.w += a1.w;
#pragma unroll
    for (int off = 4; off < 32; off <<= 1) {
        a0.x += __shfl_xor_sync(0xffffffffu, a0.x, off);
        a0.y += __shfl_xor_sync(0xffffffffu, a0.y, off);
        a0.z += __shfl_xor_sync(0xffffffffu, a0.z, off);
        a0.w += __shfl_xor_sync(0xffffffffu, a0.w, off);
    }
    return a0;
}

// ---------------------------------------------------------------------------
// Gather pass 1 + fused mid: hs2 = dinv * relu(dinv*(sum + self) + b1)
// ---------------------------------------------------------------------------
__global__ void k_gather1(const float* __restrict__ b1) {
    int tid = threadIdx.x, lane = tid & 31;
    int n = blockIdx.x * 8 + (tid >> 5);
    int eo = lane >> 2, q = lane & 3;
    int rs = g_rowp[n], re = g_fill[n];

    float4 a = warp_gather((const float4*)g_hs, g_csr, rs, re, eo, q);

    float4 sv = ((const float4*)g_hs)[(size_t)n * 4 + q];
    float di = g_dinv[n];
    float4 b = *(const float4*)(b1 + q * 4);
    float4 r;
    r.x = fmaxf(fmaf(di, a.x + sv.x, b.x), 0.f) * di;
    r.y = fmaxf(fmaf(di, a.y + sv.y, b.y), 0.f) * di;
    r.z = fmaxf(fmaf(di, a.z + sv.z, b.z), 0.f) * di;
    r.w = fmaxf(fmaf(di, a.w + sv.w, b.w), 0.f) * di;
    if (lane < 4) ((float4*)g_hs2)[(size_t)n * 4 + lane] = r;
}

// ---------------------------------------------------------------------------
// Gather pass 2 fused with GEMM2 + log_softmax
// ---------------------------------------------------------------------------
__global__ void k_gather2_final(const float* __restrict__ W2,
                                const float* __restrict__ b2,
                                float* __restrict__ out) {
    __shared__ float W2s[F_HID * F_OUT];
    __shared__ float b2s[F_OUT];
    int tid = threadIdx.x;
    for (int i = tid; i < F_HID * F_OUT; i += 256) W2s[i] = W2[i];
    if (tid < F_OUT) b2s[tid] = b2[tid];
    __syncthreads();

    int lane = tid & 31;
    int n = blockIdx.x * 8 + (tid >> 5);
    int eo = lane >> 2, q = lane & 3;
    int rs = g_rowp[n], re = g_fill[n];

    float4 a = warp_gather((const float4*)g_hs2, g_csr, rs, re, eo, q);

    float4 sv = ((const float4*)g_hs2)[(size_t)n * 4 + q];
    float di = g_dinv[n];
    float4 av;
    av.x = di * (a.x + sv.x); av.y = di * (a.y + sv.y);
    av.z = di * (a.z + sv.z); av.w = di * (a.w + sv.w);

    int jA = lane, jB = lane + 32;
    float l0 = b2s[jA];
    float l1 = (jB < F_OUT) ? b2s[jB] : -3.0e38f;
#pragma unroll
    for (int kq = 0; kq < 4; kq++) {
        float c0 = __shfl_sync(0xffffffffu, av.x, kq);
        float c1 = __shfl_sync(0xffffffffu, av.y, kq);
        float c2 = __shfl_sync(0xffffffffu, av.z, kq);
        float c3 = __shfl_sync(0xffffffffu, av.w, kq);
        const float* w = W2s + (kq * 4) * F_OUT;
        l0 = fmaf(c0, w[jA],             l0);
        l0 = fmaf(c1, w[F_OUT + jA],     l0);
        l0 = fmaf(c2, w[2 * F_OUT + jA], l0);
        l0 = fmaf(c3, w[3 * F_OUT + jA], l0);
        if (jB < F_OUT) {
            l1 = fmaf(c0, w[jB],             l1);
            l1 = fmaf(c1, w[F_OUT + jB],     l1);
            l1 = fmaf(c2, w[2 * F_OUT + jB], l1);
            l1 = fmaf(c3, w[3 * F_OUT + jB], l1);
        }
    }

    float m = fmaxf(l0, l1);
#pragma unroll
    for (int off = 16; off > 0; off >>= 1)
        m = fmaxf(m, __shfl_xor_sync(0xffffffffu, m, off));
    float s = expf(l0 - m) + ((jB < F_OUT) ? expf(l1 - m) : 0.f);
#pragma unroll
    for (int off = 16; off > 0; off >>= 1)
        s += __shfl_xor_sync(0xffffffffu, s, off);
    float lse = m + logf(s);

    float* op = out + (size_t)n * F_OUT;
    op[jA] = l0 - lse;
    if (jB < F_OUT) op[jB] = l1 - lse;
}

// ---------------------------------------------------------------------------
extern "C" void kernel_launch(void* const* d_in, const int* in_sizes, int n_in,
                              void* d_out, int out_size) {
    const float* x  = (const float*)d_in[0];
    const void*  ei = d_in[1];
    const float* W1 = (const float*)d_in[2];
    const float* b1 = (const float*)d_in[3];
    const float* W2 = (const float*)d_in[4];
    const float* b2 = (const float*)d_in[5];
    float* out = (float*)d_out;

    k_a<<<NB_GEMM + NB_CNT, 128>>>(x, W1, ei);          // gemm1 || count
    k_scan<<<(N_NODES + 1023) / 1024, 1024>>>();
    k_fill<<<6250, 256>>>(ei);
    k_gather1<<<N_NODES / 8, 256>>>(b1);
    k_gather2_final<<<N_NODES / 8, 256>>>(W2, b2, out);
}